// round 17
// baseline (speedup 1.0000x reference)
#include <cuda_runtime.h>
#include <cuda_fp16.h>
#include <cstdint>

// ============================================================
// Actor MLP via warp-level mma.sync, single-product f16 GEMM:
//   D = Af16 * Wf16 + bias   (fp32 accum, bias via MMA C-op)
// R17: (a) bias enters as the C operand of the peeled kf=0
//   MMA -> deletes 104 bias-broadcast movs/thread/layer,
//   datapath-identical numerics; (b) occupancy 3 (reg cap 170,
//   NBUF=2, smem 3x49KB) -> 3rd warp/SMSP hides the serial
//   epilogue; (c) head layer peeled out of the loop.
// 128-thread blocks (4 warps x 32 samples).
// ============================================================

#define NF 13          // n-fragments (8 wide)  -> N = 104
#define KF 7           // k-fragments (16 wide) -> K = 112
#define CHUNK 24576    // per-layer chunk stride; weights 23296B + bias 416B
#define TAILOFF 21504  // nf=12 tail region (7*256; pair region is 7*6*512)
#define BIASOFF 23296  // bias offset inside chunk
#define NLAYERS 101    // layer 0 = W_in, layers 1..100 = hidden
#define NT 128         // threads per block (4 warps x 32 samples)
#define NBUF 2
#define CPITER (CHUNK / (NT * 16))   // 12 cp.async iters per chunk per thread
#define MBOFF (NBUF * CHUNK)
#define SMTOT (MBOFF + 64)
#define C01X2 0x211F211Fu            // f16x2 {0.01, 0.01}

__device__ __align__(16) unsigned char g_WP[NLAYERS * CHUNK];    // ~2.48 MB
__device__ __align__(16) float2 g_WOUTP[NF * 4];

// ---- helpers ----
__device__ __forceinline__ uint32_t smem_u32(const void* p) {
    uint32_t a;
    asm("{ .reg .u64 t; cvta.to.shared.u64 t, %1; cvt.u32.u64 %0, t; }" : "=r"(a) : "l"(p));
    return a;
}
// pack {lower=lo_val, upper=hi_val} as f16x2 (cvt: first src -> upper half)
__device__ __forceinline__ uint32_t packh(float lo_val, float hi_val) {
    uint32_t r;
    asm("cvt.rn.f16x2.f32 %0, %1, %2;" : "=r"(r) : "f"(hi_val), "f"(lo_val));
    return r;
}
// requantize + leaky in f16x2: q=pack(a,b); max(q, 0.01*q)
__device__ __forceinline__ uint32_t leakyq(float a, float b) {
    uint32_t q = packh(a, b), m, r;
    asm("mul.f16x2 %0, %1, %2;" : "=r"(m) : "r"(q), "r"(C01X2));
    asm("max.f16x2 %0, %1, %2;" : "=r"(r) : "r"(q), "r"(m));
    return r;
}
__device__ __forceinline__ uint4 lds128(uint32_t a) {
    uint4 v;
    asm("ld.shared.v4.u32 {%0,%1,%2,%3}, [%4];"
        : "=r"(v.x), "=r"(v.y), "=r"(v.z), "=r"(v.w) : "r"(a));
    return v;
}
__device__ __forceinline__ uint2 lds64u(uint32_t a) {
    uint2 v;
    asm("ld.shared.v2.u32 {%0,%1}, [%2];" : "=r"(v.x), "=r"(v.y) : "r"(a));
    return v;
}
__device__ __forceinline__ float2 lds64f(uint32_t a) {
    float2 v;
    asm("ld.shared.v2.f32 {%0,%1}, [%2];" : "=f"(v.x), "=f"(v.y) : "r"(a));
    return v;
}
__device__ __forceinline__ void cpa16(uint32_t dst, const void* src) {
    asm volatile("cp.async.cg.shared.global [%0], [%1], 16;" :: "r"(dst), "l"(src) : "memory");
}
// ---- mbarrier primitives ----
__device__ __forceinline__ void mbar_init(uint32_t a, uint32_t cnt) {
    asm volatile("mbarrier.init.shared.b64 [%0], %1;" :: "r"(a), "r"(cnt) : "memory");
}
__device__ __forceinline__ void mbar_arrive(uint32_t a) {
    unsigned long long st;
    asm volatile("mbarrier.arrive.shared.b64 %0, [%1];" : "=l"(st) : "r"(a) : "memory");
}
__device__ __forceinline__ void mbar_wait(uint32_t a, uint32_t par) {
    asm volatile(
        "{\n\t.reg .pred P;\n\t"
        "WL%=:\n\t"
        "mbarrier.try_wait.parity.shared.b64 P, [%0], %1, 0x989680;\n\t"
        "@!P bra WL%=;\n\t}"
        :: "r"(a), "r"(par) : "memory");
}
__device__ __forceinline__ void cp_mbar_arrive(uint32_t a) {
    asm volatile("cp.async.mbarrier.arrive.noinc.shared.b64 [%0];" :: "r"(a) : "memory");
}

// accumulate: D += A*B
__device__ __forceinline__ void hmma(float* d, const uint32_t* a, uint32_t b0, uint32_t b1) {
    asm("mma.sync.aligned.m16n8k16.row.col.f32.f16.f16.f32 "
        "{%0,%1,%2,%3}, {%4,%5,%6,%7}, {%8,%9}, {%0,%1,%2,%3};"
        : "+f"(d[0]), "+f"(d[1]), "+f"(d[2]), "+f"(d[3])
        : "r"(a[0]), "r"(a[1]), "r"(a[2]), "r"(a[3]), "r"(b0), "r"(b1));
}
// init: D = A*B + {cx,cy,cx,cy}  (bias as C operand; same datapath as
// init-D-to-bias-then-accumulate, so numerics are identical)
__device__ __forceinline__ void hmma_init(float* d, const uint32_t* a,
                                          uint32_t b0, uint32_t b1,
                                          float cx, float cy) {
    asm("mma.sync.aligned.m16n8k16.row.col.f32.f16.f16.f32 "
        "{%0,%1,%2,%3}, {%4,%5,%6,%7}, {%8,%9}, {%10,%11,%10,%11};"
        : "=f"(d[0]), "=f"(d[1]), "=f"(d[2]), "=f"(d[3])
        : "r"(a[0]), "r"(a[1]), "r"(a[2]), "r"(a[3]), "r"(b0), "r"(b1),
          "f"(cx), "f"(cy));
}
// fp32 leaky (head only)
__device__ __forceinline__ float leaky(float v) {
    float m = 0.01f * v, r;
    asm("slct.f32.f32 %0, %1, %2, %3;" : "=f"(r) : "f"(v), "f"(m), "f"(v));
    return r;
}

// ============================================================
// prep: fragment-permuted f16 weights, nf-PAIR contiguous:
//  nf<12: uint4 @ L*CHUNK + (kf*6 + nf/2)*512 + lane*16 + (nf&1)*8
//  nf=12: uint2 @ L*CHUNK + TAILOFF + kf*256 + lane*8
//  with n = nf*8 + lane/4, k = kf*16 + 2*(lane%4)
// bias (float2 per (nf,q)) @ L*CHUNK + BIASOFF + (nf*4+q)*8
// ============================================================
#define NWT (NLAYERS * KF * NF * 32)
__global__ void prep(const float* __restrict__ W_in, const float* __restrict__ b_in,
                     const float* __restrict__ Ws, const float* __restrict__ bs,
                     const float* __restrict__ W_out) {
    int t = blockIdx.x * 256 + threadIdx.x;
    if (t < NWT) {
        int L = t / (KF * NF * 32);
        int r = t % (KF * NF * 32);
        int kf = r / (NF * 32);
        int r2 = r % (NF * 32);
        int nf = r2 / 32, lane = r2 % 32;
        int n = nf * 8 + (lane >> 2);
        int k = kf * 16 + 2 * (lane & 3);
        float v[4];  // (k, k+1, k+8, k+9)
#pragma unroll
        for (int e = 0; e < 4; e++) {
            int kk = k + (e & 1) + (e >> 1) * 8;
            float w = 0.0f;
            if (L == 0) {
                if (kk < 64 && n < 100) w = W_in[kk * 100 + n];
            } else {
                if (kk < 100 && n < 100) w = Ws[((size_t)(L - 1) * 100 + kk) * 100 + n];
            }
            v[e] = w;
        }
        __half2 hp0 = __halves2half2(__float2half_rn(v[0]), __float2half_rn(v[1]));
        __half2 hp1 = __halves2half2(__float2half_rn(v[2]), __float2half_rn(v[3]));
        size_t off;
        if (nf < 12) {
            off = (size_t)L * CHUNK + ((size_t)(kf * 6 + (nf >> 1)) * 512)
                + (size_t)lane * 16 + (size_t)(nf & 1) * 8;
        } else {
            off = (size_t)L * CHUNK + TAILOFF + (size_t)kf * 256 + (size_t)lane * 8;
        }
        *(uint2*)(g_WP + off) = make_uint2(*(uint32_t*)&hp0, *(uint32_t*)&hp1);
        return;
    }
    t -= NWT;
    if (t < NLAYERS * NF * 4) {
        int m = t / (NF * 4);
        int r = t % (NF * 4);
        int nf = r / 4, q = r % 4;
        int c = nf * 8 + 2 * q;
        float b0 = (c < 100)     ? (m == 0 ? b_in[c]     : bs[(m - 1) * 100 + c])     : 0.0f;
        float b1 = (c + 1 < 100) ? (m == 0 ? b_in[c + 1] : bs[(m - 1) * 100 + c + 1]) : 0.0f;
        *(float2*)(g_WP + (size_t)m * CHUNK + BIASOFF + (size_t)r * 8) = make_float2(b0, b1);
        return;
    }
    t -= NLAYERS * NF * 4;
    if (t < NF * 4) {
        int nf = t / 4, q = t % 4;
        int c = nf * 8 + 2 * q;
        g_WOUTP[t] = make_float2(c < 100 ? W_out[c] : 0.0f,
                                 c + 1 < 100 ? W_out[c + 1] : 0.0f);
    }
}

// ============================================================
// GEMM for one layer into D[NF][8] (bias fused via kf=0 C-op)
// accumulation order per D[nf]: bias, then kf ascending
// ============================================================
__device__ __forceinline__ void layer_gemm(
    uint32_t bufA, int lane,
    const uint32_t (&A0)[KF][4], const uint32_t (&A1)[KF][4],
    float (&D)[NF][8])
{
    // kf = 0 peel: D = A*W + bias
    {
        uint32_t adp = bufA + (uint32_t)lane * 16;
        uint32_t ba  = bufA + BIASOFF + (uint32_t)(lane & 3) * 8;
#pragma unroll
        for (int np = 0; np < 6; np++) {
            uint4 w = lds128(adp);
            float2 bv0 = lds64f(ba + (uint32_t)(2 * np) * 32);
            float2 bv1 = lds64f(ba + (uint32_t)(2 * np + 1) * 32);
            hmma_init(&D[2*np][0],   A0[0], w.x, w.y, bv0.x, bv0.y);
            hmma_init(&D[2*np][4],   A1[0], w.x, w.y, bv0.x, bv0.y);
            hmma_init(&D[2*np+1][0], A0[0], w.z, w.w, bv1.x, bv1.y);
            hmma_init(&D[2*np+1][4], A1[0], w.z, w.w, bv1.x, bv1.y);
            adp += 512;
        }
        uint2 wt = lds64u(bufA + TAILOFF + (uint32_t)lane * 8);
        float2 bvt = lds64f(ba + 12u * 32);
        hmma_init(&D[12][0], A0[0], wt.x, wt.y, bvt.x, bvt.y);
        hmma_init(&D[12][4], A1[0], wt.x, wt.y, bvt.x, bvt.y);
    }
    // kf = 1..6: accumulate
#pragma unroll
    for (int kf = 1; kf < KF; kf++) {
        uint32_t adp = bufA + (uint32_t)(kf * 6) * 512 + (uint32_t)lane * 16;
#pragma unroll
        for (int np = 0; np < 6; np++) {
            uint4 w = lds128(adp);
            hmma(&D[2*np][0],   A0[kf], w.x, w.y);
            hmma(&D[2*np][4],   A1[kf], w.x, w.y);
            hmma(&D[2*np+1][0], A0[kf], w.z, w.w);
            hmma(&D[2*np+1][4], A1[kf], w.z, w.w);
            adp += 512;
        }
        uint2 wt = lds64u(bufA + TAILOFF + (uint32_t)kf * 256 + (uint32_t)lane * 8);
        hmma(&D[12][0], A0[kf], wt.x, wt.y);
        hmma(&D[12][4], A1[kf], wt.x, wt.y);
    }
}

// ============================================================
// main kernel: 128 threads (4 warps x 32 samples), occupancy 3,
// double-buffered weights, mbarrier-only sync
// ============================================================
__global__ void __launch_bounds__(NT, 3)
actor(const float* __restrict__ x, const float* __restrict__ b_out,
      float* __restrict__ out, int nsamples) {
    extern __shared__ unsigned char sm[];
    const uint32_t smb = smem_u32(sm);
    const uint32_t mbF = smb + MBOFF;        // full[b] at +b*8
    const uint32_t mbE = smb + MBOFF + 16;   // free[b] at +b*8
    const int tid = threadIdx.x, lane = tid & 31, warp = tid >> 5;
    const int s0 = blockIdx.x * NT + warp * 32;
    const int r = lane >> 2, kc = 2 * (lane & 3);

    if (tid == 0) {
#pragma unroll
        for (int b = 0; b < NBUF; b++) {
            mbar_init(mbF + b * 8, NT);
            mbar_init(mbE + b * 8, NT);
        }
    }
    __syncthreads();

    // ---- prologue: fill buffers 0..1 with layers 0..1 ----
#pragma unroll
    for (int L = 0; L < NBUF; L++) {
        const unsigned char* sp = g_WP + (size_t)L * CHUNK + tid * 16;
        uint32_t dp = smb + (uint32_t)L * CHUNK + tid * 16;
#pragma unroll
        for (int i = 0; i < CPITER; i++) cpa16(dp + i * (NT * 16), sp + (size_t)i * (NT * 16));
        cp_mbar_arrive(mbF + L * 8);
    }

    // ---- layer-0 A fragments (f16) straight from x ----
    uint32_t A0[KF][4], A1[KF][4];
    {
        const bool v0 = (s0 + r)      < nsamples;
        const bool v1 = (s0 + r + 8)  < nsamples;
        const bool v2 = (s0 + r + 16) < nsamples;
        const bool v3 = (s0 + r + 24) < nsamples;
        const float* xb = x + (size_t)s0 * 64;
#pragma unroll
        for (int kf = 0; kf < 4; kf++) {
            int k = kf * 16 + kc;
            float2 pa0 = v0 ? *(const float2*)(xb + (size_t)r * 64 + k)            : make_float2(0.f, 0.f);
            float2 pa1 = v0 ? *(const float2*)(xb + (size_t)r * 64 + k + 8)        : make_float2(0.f, 0.f);
            float2 pb0 = v1 ? *(const float2*)(xb + (size_t)(r + 8) * 64 + k)      : make_float2(0.f, 0.f);
            float2 pb1 = v1 ? *(const float2*)(xb + (size_t)(r + 8) * 64 + k + 8)  : make_float2(0.f, 0.f);
            float2 pc0 = v2 ? *(const float2*)(xb + (size_t)(r + 16) * 64 + k)     : make_float2(0.f, 0.f);
            float2 pc1 = v2 ? *(const float2*)(xb + (size_t)(r + 16) * 64 + k + 8) : make_float2(0.f, 0.f);
            float2 pd0 = v3 ? *(const float2*)(xb + (size_t)(r + 24) * 64 + k)     : make_float2(0.f, 0.f);
            float2 pd1 = v3 ? *(const float2*)(xb + (size_t)(r + 24) * 64 + k + 8) : make_float2(0.f, 0.f);
            A0[kf][0] = packh(pa0.x, pa0.y);
            A0[kf][1] = packh(pb0.x, pb0.y);
            A0[kf][2] = packh(pa1.x, pa1.y);
            A0[kf][3] = packh(pb1.x, pb1.y);
            A1[kf][0] = packh(pc0.x, pc0.y);
            A1[kf][1] = packh(pd0.x, pd0.y);
            A1[kf][2] = packh(pc1.x, pc1.y);
            A1[kf][3] = packh(pd1.x, pd1.y);
        }
#pragma unroll
        for (int kf = 4; kf < KF; kf++) {
            A0[kf][0] = A0[kf][1] = A0[kf][2] = A0[kf][3] = 0u;
            A1[kf][0] = A1[kf][1] = A1[kf][2] = A1[kf][3] = 0u;
        }
    }

    int b = 0;
    uint32_t par = 0;

    // ---- layers 0..99: GEMM + requantize epilogue ----
#pragma unroll 1
    for (int m = 0; m < 100; m++) {
        const uint32_t bufA = smb + (uint32_t)b * CHUNK;
        mbar_wait(mbF + b * 8, par);

        float D[NF][8];
        layer_gemm(bufA, lane, A0, A1, D);

        mbar_arrive(mbE + b * 8);

        // epilogue: requantize + packed-f16 leaky
#pragma unroll
        for (int t2 = 0; t2 < 6; t2++) {
            const float* d0 = D[2 * t2];
            const float* d1 = D[2 * t2 + 1];
            A0[t2][0] = leakyq(d0[0], d0[1]);
            A0[t2][1] = leakyq(d0[2], d0[3]);
            A0[t2][2] = leakyq(d1[0], d1[1]);
            A0[t2][3] = leakyq(d1[2], d1[3]);
            A1[t2][0] = leakyq(d0[4], d0[5]);
            A1[t2][1] = leakyq(d0[6], d0[7]);
            A1[t2][2] = leakyq(d1[4], d1[5]);
            A1[t2][3] = leakyq(d1[6], d1[7]);
        }
        {
            const float* d0 = D[12];
            A0[6][0] = leakyq(d0[0], d0[1]);
            A0[6][1] = leakyq(d0[2], d0[3]);
            A0[6][2] = 0u; A0[6][3] = 0u;
            A1[6][0] = leakyq(d0[4], d0[5]);
            A1[6][1] = leakyq(d0[6], d0[7]);
            A1[6][2] = 0u; A1[6][3] = 0u;
        }

        // refill buffer b with layer m+2
        if (m + 2 <= 100) {
            mbar_wait(mbE + b * 8, par);
            const unsigned char* sp = g_WP + (size_t)(m + 2) * CHUNK + tid * 16;
            uint32_t dp = bufA + tid * 16;
#pragma unroll
            for (int i = 0; i < CPITER; i++) cpa16(dp + i * (NT * 16), sp + (size_t)i * (NT * 16));
            cp_mbar_arrive(mbF + b * 8);
        }

        if (++b == NBUF) { b = 0; par ^= 1u; }
    }

    // ---- head layer m=100 (buffer b, then W_out dot) ----
    float po0, po1, po2, po3;
    {
        const uint32_t bufA = smb + (uint32_t)b * CHUNK;
        mbar_wait(mbF + b * 8, par);

        float D[NF][8];
        layer_gemm(bufA, lane, A0, A1, D);

        po0 = po1 = po2 = po3 = 0.0f;
#pragma unroll
        for (int nf = 0; nf < NF; nf++) {
            float2 w = g_WOUTP[nf * 4 + (lane & 3)];
            po0 += leaky(D[nf][0]) * w.x + leaky(D[nf][1]) * w.y;
            po1 += leaky(D[nf][2]) * w.x + leaky(D[nf][3]) * w.y;
            po2 += leaky(D[nf][4]) * w.x + leaky(D[nf][5]) * w.y;
            po3 += leaky(D[nf][6]) * w.x + leaky(D[nf][7]) * w.y;
        }
    }

    // ---- head reduce across the 4 lanes sharing a row ----
    po0 += __shfl_xor_sync(0xffffffff, po0, 1);
    po0 += __shfl_xor_sync(0xffffffff, po0, 2);
    po1 += __shfl_xor_sync(0xffffffff, po1, 1);
    po1 += __shfl_xor_sync(0xffffffff, po1, 2);
    po2 += __shfl_xor_sync(0xffffffff, po2, 1);
    po2 += __shfl_xor_sync(0xffffffff, po2, 2);
    po3 += __shfl_xor_sync(0xffffffff, po3, 1);
    po3 += __shfl_xor_sync(0xffffffff, po3, 2);
    if ((lane & 3) == 0) {
        float bo = b_out[0];
        if (s0 + r      < nsamples) out[s0 + r]      = tanhf(po0 + bo) * 4.5f + 5.5f;
        if (s0 + r + 8  < nsamples) out[s0 + r + 8]  = tanhf(po1 + bo) * 4.5f + 5.5f;
        if (s0 + r + 16 < nsamples) out[s0 + r + 16] = tanhf(po2 + bo) * 4.5f + 5.5f;
        if (s0 + r + 24 < nsamples) out[s0 + r + 24] = tanhf(po3 + bo) * 4.5f + 5.5f;
    }
}

extern "C" void kernel_launch(void* const* d_in, const int* in_sizes, int n_in,
                              void* d_out, int out_size) {
    const float* x     = (const float*)d_in[0];
    const float* W_in  = (const float*)d_in[1];
    const float* b_in  = (const float*)d_in[2];
    const float* Ws    = (const float*)d_in[3];
    const float* bs    = (const float*)d_in[4];
    const float* W_out = (const float*)d_in[5];
    const float* b_out = (const float*)d_in[6];
    float* out = (float*)d_out;

    int nsamples = in_sizes[0] / 64;
    int nblocks  = (nsamples + NT - 1) / NT;

    const int PREP_TOTAL = NWT + NLAYERS * NF * 4 + NF * 4;
    prep<<<(PREP_TOTAL + 255) / 256, 256>>>(W_in, b_in, Ws, bs, W_out);

    cudaFuncSetAttribute(actor, cudaFuncAttributeMaxDynamicSharedMemorySize, SMTOT);
    actor<<<nblocks, NT, SMTOT>>>(x, b_out, out, nsamples);
}